// round 5
// baseline (speedup 1.0000x reference)
#include <cuda_runtime.h>
#include <cuda_bf16.h>
#include <math.h>
#include <stdint.h>

// ---------------- problem constants ----------------
#define BB   2
#define TT   4096
#define HH   8
#define EE   64
#define MM   256
#define NHSH 4
#define BHN  16            // B*H
#define BHT  (BHN*TT)      // 65536
#define NB   32            // buckets per (hash, bh)
#define BS   128           // bucket size

#define TEMP   0.125f                 // 1/sqrt(64)
#define DN     0.3535533905932738f    // sqrt(TEMP)
#define RATIO  0.0625f                // 256^-0.5

// ---------------- scratch (device globals; no runtime alloc) ----------------
__device__ float g_q[BHT*EE];
__device__ float g_k[BHT*EE];
__device__ float g_v[BHT*EE];
__device__ float g_qn2[BHT], g_kn2[BHT];
__device__ float g_MQ2[BHN], g_MK2[BHN];
__device__ unsigned long long g_qkeys[NHSH*BHT];
__device__ unsigned long long g_kkeys[NHSH*BHT];
__device__ int g_qpos[NHSH*BHT], g_kpos[NHSH*BHT];
__device__ int g_qrev[NHSH*BHT], g_krev[NHSH*BHT];
__device__ float g_qp[BHT*MM];         // q_prime
__device__ float g_kp[BHT*MM];         // k logv then k_prime
__device__ float g_qls[BHT];           // per-row q stabilizer
__device__ float g_krowmax[BHT];
__device__ float g_kls[BHN];           // per-bh k stabilizer
__device__ float g_kv[BHN*MM*EE];
__device__ float g_ksum[BHN*MM];
__device__ float g_qkv[BHT*EE];
__device__ float g_qk1[BHT];
__device__ float g_o[NHSH*BHT*EE];     // per-hash bucket outputs (scattered)
__device__ float g_logits[NHSH*BHT];
__device__ float g_dsum[NHSH*BHT];

// ---------------- helpers ----------------
__device__ __forceinline__ unsigned f2sortable(float f) {
    unsigned u = __float_as_uint(f);
    return (u & 0x80000000u) ? ~u : (u | 0x80000000u);
}

__device__ __forceinline__ float f2tf32(float x) {
    asm("cvt.rna.tf32.f32 %0, %0;" : "+f"(x));
    return x;
}

// tf32 mma.sync m16n8k8 (sm_80+ path, works on family target sm_103)
__device__ __forceinline__ void mma16n8k8(float* d, const uint32_t* a, const uint32_t* b) {
    asm volatile(
        "mma.sync.aligned.m16n8k8.row.col.f32.tf32.tf32.f32 "
        "{%0,%1,%2,%3}, {%4,%5,%6,%7}, {%8,%9}, {%0,%1,%2,%3};"
        : "+f"(d[0]), "+f"(d[1]), "+f"(d[2]), "+f"(d[3])
        : "r"(a[0]), "r"(a[1]), "r"(a[2]), "r"(a[3]), "r"(b[0]), "r"(b[1]));
}

// ---------------- K0: transpose (B,T,H,E)->(bh,T,E) + row norms ----------------
__global__ void k_transpose(const float* __restrict__ q, const float* __restrict__ k,
                            const float* __restrict__ v) {
    __shared__ float sred[8][2];
    int tid = threadIdx.x;
    int g = tid >> 6;          // 0..3 rows per block
    int e = tid & 63;
    int row = blockIdx.x * 4 + g;
    int bh = row >> 12;
    int t  = row & 4095;
    int b = bh >> 3, h = bh & 7;
    int src = ((b * TT + t) * HH + h) * EE + e;
    float qv = q[src], kv2 = k[src], vv = v[src];
    g_q[row*EE+e] = qv; g_k[row*EE+e] = kv2; g_v[row*EE+e] = vv;
    float sq = qv*qv, sk = kv2*kv2;
    #pragma unroll
    for (int m = 16; m > 0; m >>= 1) {
        sq += __shfl_xor_sync(0xffffffffu, sq, m);
        sk += __shfl_xor_sync(0xffffffffu, sk, m);
    }
    int w = tid >> 5;
    if ((tid & 31) == 0) { sred[w][0] = sq; sred[w][1] = sk; }
    __syncthreads();
    if (e == 0) {
        g_qn2[row] = sred[2*g][0] + sred[2*g+1][0];
        g_kn2[row] = sred[2*g][1] + sred[2*g+1][1];
    }
}

// ---------------- K1: per-bh max of squared norms ----------------
__global__ void k_maxnorm() {
    __shared__ float s[8][2];
    int bh = blockIdx.x, tid = threadIdx.x;
    float mq = 0.f, mk = 0.f;
    for (int t = tid; t < TT; t += 256) {
        mq = fmaxf(mq, g_qn2[bh*TT+t]);
        mk = fmaxf(mk, g_kn2[bh*TT+t]);
    }
    #pragma unroll
    for (int m = 16; m > 0; m >>= 1) {
        mq = fmaxf(mq, __shfl_xor_sync(0xffffffffu, mq, m));
        mk = fmaxf(mk, __shfl_xor_sync(0xffffffffu, mk, m));
    }
    if ((tid & 31) == 0) { s[tid>>5][0] = mq; s[tid>>5][1] = mk; }
    __syncthreads();
    if (tid == 0) {
        float a = s[0][0], b2 = s[0][1];
        for (int i = 1; i < 8; i++) { a = fmaxf(a, s[i][0]); b2 = fmaxf(b2, s[i][1]); }
        g_MQ2[bh] = a; g_MK2[bh] = b2;
    }
}

// ---------------- K2: LSH hash keys (packed sortable key | index) ----------------
__global__ void k_hash(const float* __restrict__ alpha, const float* __restrict__ beta) {
    int w = threadIdx.x >> 5, lane = threadIdx.x & 31;
    int row = blockIdx.x * 8 + w;
    int bh = row >> 12, t = row & 4095;
    float aq[NHSH] = {0,0,0,0}, ak[NHSH] = {0,0,0,0};
    for (int e = lane; e < EE; e += 32) {
        float xq = g_q[row*EE+e], xk = g_k[row*EE+e];
        #pragma unroll
        for (int h = 0; h < NHSH; h++) {
            float al = alpha[e*NHSH+h];
            aq[h] = fmaf(xq, al, aq[h]);
            ak[h] = fmaf(xk, al, ak[h]);
        }
    }
    #pragma unroll
    for (int m = 16; m > 0; m >>= 1) {
        #pragma unroll
        for (int h = 0; h < NHSH; h++) {
            aq[h] += __shfl_xor_sync(0xffffffffu, aq[h], m);
            ak[h] += __shfl_xor_sync(0xffffffffu, ak[h], m);
        }
    }
    if (lane == 0) {
        float s2 = g_MQ2[bh] + g_MK2[bh];
        float extq = sqrtf(fmaxf(s2 - g_qn2[row], 0.f));
        float extk = sqrtf(fmaxf(s2 - g_kn2[row], 0.f));
        #pragma unroll
        for (int h = 0; h < NHSH; h++) {
            float hq = aq[h] + extq * alpha[64*NHSH+h] + beta[h];
            float hk = ak[h] + extk * alpha[65*NHSH+h] + beta[h];
            g_qkeys[(h*BHN+bh)*TT + t] = (((unsigned long long)f2sortable(hq)) << 32) | (unsigned)t;
            g_kkeys[(h*BHN+bh)*TT + t] = (((unsigned long long)f2sortable(hk)) << 32) | (unsigned)t;
        }
    }
}

// ---------------- K3: bitonic argsort (stable via packed index) ----------------
__global__ void k_sort() {
    __shared__ unsigned long long s[TT];
    int which = blockIdx.x >> 6;                 // 0 = q, 1 = k
    int hb = blockIdx.x & 63;
    const unsigned long long* src = which ? g_kkeys : g_qkeys;
    int* pos = which ? g_kpos : g_qpos;
    int* rev = which ? g_krev : g_qrev;
    int base = hb * TT;
    for (int i = threadIdx.x; i < TT; i += 512) s[i] = src[base+i];
    for (int k2 = 2; k2 <= TT; k2 <<= 1) {
        for (int j = k2 >> 1; j > 0; j >>= 1) {
            __syncthreads();
            for (int i = threadIdx.x; i < TT; i += 512) {
                int ixj = i ^ j;
                if (ixj > i) {
                    unsigned long long a = s[i], b = s[ixj];
                    bool asc = ((i & k2) == 0);
                    if ((a > b) == asc) { s[i] = b; s[ixj] = a; }
                }
            }
        }
    }
    __syncthreads();
    for (int i = threadIdx.x; i < TT; i += 512) {
        int orig = (int)(s[i] & 0xffffffffu);
        pos[base+i] = orig;
        rev[base+orig] = i;
    }
}

// ---------------- K4: q Performer features (per-row stabilizer) ----------------
__global__ void k_feats_q(const float* __restrict__ proj) {
    extern __shared__ float sm[];
    float* qrow = sm;       // 64
    float* red  = sm + 64;  // 9
    int tid = threadIdx.x;
    float pcol[EE];
    const float4* p4 = (const float4*)(proj + tid*EE);
    #pragma unroll
    for (int i = 0; i < 16; i++) {
        float4 w = p4[i];
        pcol[4*i] = w.x; pcol[4*i+1] = w.y; pcol[4*i+2] = w.z; pcol[4*i+3] = w.w;
    }
    int row0 = blockIdx.x * 16;
    for (int r = 0; r < 16; r++) {
        int row = row0 + r;
        if (tid < 64) qrow[tid] = g_q[row*EE+tid];
        __syncthreads();
        float dot = 0.f;
        #pragma unroll
        for (int e = 0; e < EE; e++) dot = fmaf(qrow[e], pcol[e], dot);
        float logv = DN * dot - 0.0625f * g_qn2[row];   // 0.5*dn^2 = 0.0625
        float mx = logv;
        #pragma unroll
        for (int m = 16; m > 0; m >>= 1) mx = fmaxf(mx, __shfl_xor_sync(0xffffffffu, mx, m));
        if ((tid & 31) == 0) red[tid>>5] = mx;
        __syncthreads();
        if (tid == 0) {
            float a = red[0];
            for (int i = 1; i < 8; i++) a = fmaxf(a, red[i]);
            red[8] = a;
        }
        __syncthreads();
        float stab = red[8];
        g_qp[row*MM+tid] = expf(logv - stab) * RATIO;
        if (tid == 0) g_qls[row] = stab;
        __syncthreads();
    }
}

// ---------------- K5: k features pass1 (logv + row max) ----------------
__global__ void k_feats_k(const float* __restrict__ proj) {
    extern __shared__ float sm[];
    float* krow = sm;
    float* red  = sm + 64;
    int tid = threadIdx.x;
    float pcol[EE];
    const float4* p4 = (const float4*)(proj + tid*EE);
    #pragma unroll
    for (int i = 0; i < 16; i++) {
        float4 w = p4[i];
        pcol[4*i] = w.x; pcol[4*i+1] = w.y; pcol[4*i+2] = w.z; pcol[4*i+3] = w.w;
    }
    int row0 = blockIdx.x * 16;
    for (int r = 0; r < 16; r++) {
        int row = row0 + r;
        if (tid < 64) krow[tid] = g_k[row*EE+tid];
        __syncthreads();
        float dot = 0.f;
        #pragma unroll
        for (int e = 0; e < EE; e++) dot = fmaf(krow[e], pcol[e], dot);
        float logv = DN * dot - 0.0625f * g_kn2[row];
        float mx = logv;
        #pragma unroll
        for (int m = 16; m > 0; m >>= 1) mx = fmaxf(mx, __shfl_xor_sync(0xffffffffu, mx, m));
        if ((tid & 31) == 0) red[tid>>5] = mx;
        __syncthreads();
        if (tid == 0) {
            float a = red[0];
            for (int i = 1; i < 8; i++) a = fmaxf(a, red[i]);
            red[8] = a;
        }
        __syncthreads();
        g_kp[row*MM+tid] = logv;
        if (tid == 0) g_krowmax[row] = red[8];
        __syncthreads();
    }
}

// ---------------- K6: per-bh k stabilizer ----------------
__global__ void k_kls() {
    __shared__ float s[8];
    int bh = blockIdx.x, tid = threadIdx.x;
    float m = -3.402823466e38f;
    for (int t = tid; t < TT; t += 256) m = fmaxf(m, g_krowmax[bh*TT+t]);
    #pragma unroll
    for (int mm = 16; mm > 0; mm >>= 1) m = fmaxf(m, __shfl_xor_sync(0xffffffffu, m, mm));
    if ((tid & 31) == 0) s[tid>>5] = m;
    __syncthreads();
    if (tid == 0) {
        float a = s[0];
        for (int i = 1; i < 8; i++) a = fmaxf(a, s[i]);
        g_kls[bh] = a;
    }
}

// ---------------- K7: k_prime = exp(logv - kls)*ratio ----------------
__global__ void k_kexp() {
    int idx4 = blockIdx.x * 256 + threadIdx.x;      // float4 index
    int bh = idx4 >> 18;                            // (4096*256)/4 = 2^18 per bh
    float kls = g_kls[bh];
    float4* p = (float4*)g_kp;
    float4 x = p[idx4];
    x.x = expf(x.x - kls) * RATIO;
    x.y = expf(x.y - kls) * RATIO;
    x.z = expf(x.z - kls) * RATIO;
    x.w = expf(x.w - kls) * RATIO;
    p[idx4] = x;
}

// ---------------- K8: zero kv/ksum ----------------
__global__ void k_zero() {
    int i = blockIdx.x * 256 + threadIdx.x;
    if (i < BHN*MM*EE) g_kv[i] = 0.f;
    if (i < BHN*MM) g_ksum[i] = 0.f;
}

// ---------------- K9: kv = k_prime^T @ v, ksum = sum_s k_prime ----------------
__global__ void k_kvker() {
    __shared__ float vs[128*EE];
    int bh = blockIdx.y, sc = blockIdx.x, tid = threadIdx.x;
    int s0 = sc * 128;
    for (int i = tid; i < 128*EE; i += 256) vs[i] = g_v[(bh*TT+s0)*EE + i];
    __syncthreads();
    float acc[EE];
    #pragma unroll
    for (int d = 0; d < EE; d++) acc[d] = 0.f;
    float asum = 0.f;
    int m = tid;
    const float* kp = g_kp + ((size_t)(bh*TT+s0))*MM + m;
    for (int s = 0; s < 128; s++) {
        float kpv = kp[(size_t)s*MM];
        asum += kpv;
        #pragma unroll
        for (int d = 0; d < EE; d++) acc[d] = fmaf(kpv, vs[s*EE+d], acc[d]);
    }
    float* kvp = g_kv + (bh*MM+m)*EE;
    #pragma unroll
    for (int d = 0; d < EE; d++) atomicAdd(kvp + d, acc[d]);
    atomicAdd(g_ksum + bh*MM+m, asum);
}

// ---------------- K10: qkv = q_prime @ kv (kv transposed in smem, float4) ----------------
#define QKV_PITCH 260
__global__ void __launch_bounds__(256) k_qkvker() {
    extern __shared__ float kvT[];   // 64 * 260 floats
    int tid = threadIdx.x;
    int bh = blockIdx.x >> 5;        // 32 blocks per bh
    int t0 = (blockIdx.x & 31) * 128;
    for (int idx = tid; idx < MM*16; idx += 256) {
        int m = idx >> 4, d4 = idx & 15;
        float4 w = *(const float4*)&g_kv[(bh*MM+m)*EE + d4*4];
        kvT[(d4*4+0)*QKV_PITCH+m] = w.x;
        kvT[(d4*4+1)*QKV_PITCH+m] = w.y;
        kvT[(d4*4+2)*QKV_PITCH+m] = w.z;
        kvT[(d4*4+3)*QKV_PITCH+m] = w.w;
    }
    __syncthreads();
    int dl = tid & 63, rg = tid >> 6;
    for (int s = 0; s < 8; s++) {
        float acc[4] = {0.f, 0.f, 0.f, 0.f};
        int rowb = bh*TT + t0 + s*16;
        #pragma unroll 4
        for (int m4 = 0; m4 < 64; m4++) {
            float4 kv4 = *(const float4*)&kvT[dl*QKV_PITCH + m4*4];
            #pragma unroll
            for (int r = 0; r < 4; r++) {
                float4 q4 = *(const float4*)&g_qp[(size_t)(rowb + rg + r*4)*MM + m4*4];
                acc[r] = fmaf(q4.x, kv4.x, acc[r]);
                acc[r] = fmaf(q4.y, kv4.y, acc[r]);
                acc[r] = fmaf(q4.z, kv4.z, acc[r]);
                acc[r] = fmaf(q4.w, kv4.w, acc[r]);
            }
        }
        #pragma unroll
        for (int r = 0; r < 4; r++)
            g_qkv[(size_t)(rowb + rg + r*4)*EE + dl] = acc[r];
    }
}

// ---------------- K11: qk1 = q_prime . ksum ----------------
__global__ void k_qk1ker() {
    int w = threadIdx.x >> 5, lane = threadIdx.x & 31;
    int row = blockIdx.x * 8 + w;
    int bh = row >> 12;
    const float* qp = g_qp + (size_t)row*MM;
    const float* ks = g_ksum + bh*MM;
    float a = 0.f;
    for (int m = lane; m < MM; m += 32) a = fmaf(qp[m], ks[m], a);
    #pragma unroll
    for (int m = 16; m > 0; m >>= 1) a += __shfl_xor_sync(0xffffffffu, a, m);
    if (lane == 0) g_qk1[row] = a;
}

// ---------------- K12: per-bucket attention — tf32 mma.sync version ----------------
// smem float layout (27520 floats = 110080 B):
//  bufQ [0, 8704)      : 128 x pitch 68 (tf32 tiles: q, then qp chunks)
//  bufK [8704, 17408)  : 128 x pitch 68 (k, then kp chunks)
//  dots overlays [0, 16512): pitch 129
//  sv   [17408, 25856) : 128 x pitch 66... NO: pitch 68 (float4-aligned)
//  qi 26112, ki 26240, qb 26368, kb 26496, pls 26624,
//  pmax 26752 (512), psum 27264 (512) -> total 27776
#define SV_OFF   17408
#define QI_OFF   26112
#define BK_FLOATS 27776
__global__ void __launch_bounds__(512, 1) k_bucket() {
    extern __shared__ float sm[];
    float* bufQ = sm;
    float* bufK = sm + 8704;
    float* dots = sm;                   // pitch 129, overlays bufQ/bufK
    float* sv   = sm + SV_OFF;          // pitch 68
    int*      qi = (int*)(sm + QI_OFF);
    int*      ki = (int*)(sm + QI_OFF + 128);
    unsigned* qb = (unsigned*)(sm + QI_OFF + 256);
    unsigned* kb = (unsigned*)(sm + QI_OFF + 384);
    float*   pls = sm + QI_OFF + 512;
    float*  pmax = sm + QI_OFF + 640;
    float*  psum = sm + QI_OFF + 1152;

    int tid = threadIdx.x;
    int n  = blockIdx.x & 31;
    int bh = (blockIdx.x >> 5) & 15;
    int h  = blockIdx.x >> 9;
    int hb = h * BHN + bh;

    if (tid < 128) qi[tid] = g_qpos[hb*TT + n*128 + tid];
    else if (tid < 256) ki[tid-128] = g_kpos[hb*TT + n*128 + (tid-128)];
    __syncthreads();

    // ---- stage q,k (tf32), v (fp32), bucket ids ----
    for (int t2 = tid; t2 < 2048; t2 += 512) {
        int r = t2 >> 4, c4 = (t2 & 15) << 2;
        int qrow = bh*TT + qi[r], krow = bh*TT + ki[r];
        float4 a = *(const float4*)&g_q[(size_t)qrow*EE + c4];
        float4 b = *(const float4*)&g_k[(size_t)krow*EE + c4];
        float4 c = *(const float4*)&g_v[(size_t)krow*EE + c4];
        a.x = f2tf32(a.x); a.y = f2tf32(a.y); a.z = f2tf32(a.z); a.w = f2tf32(a.w);
        b.x = f2tf32(b.x); b.y = f2tf32(b.y); b.z = f2tf32(b.z); b.w = f2tf32(b.w);
        *(float4*)&bufQ[r*68 + c4] = a;
        *(float4*)&bufK[r*68 + c4] = b;
        *(float4*)&sv[r*68 + c4] = c;
    }
    if (tid < 128) {
        int q0 = qi[tid];
        unsigned pb = 0;
        #pragma unroll
        for (int hh = 0; hh < NHSH; hh++)
            pb |= ((unsigned)(g_qrev[(hh*BHN+bh)*TT + q0] >> 7)) << (8*hh);
        qb[tid] = pb;
        pls[tid] = g_qls[bh*TT + q0] + g_kls[bh];
    } else if (tid < 256) {
        int j = tid - 128;
        int k0 = ki[j];
        unsigned pb = 0;
        #pragma unroll
        for (int hh = 0; hh < NHSH; hh++)
            pb |= ((unsigned)(g_krev[(hh*BHN+bh)*TT + k0] >> 7)) << (8*hh);
        kb[j] = pb;
    }
    __syncthreads();

    int wid = tid >> 5, lane = tid & 31;
    int wr = wid >> 2, wc = wid & 3;
    int g = lane >> 2, t = lane & 3;
    const int arow = (wr*32 + g)*68 + t;    // A frag base (mt=0, reg0)
    const int brow = (wc*32 + g)*68 + t;    // B frag base (nt=0, reg0)

    float accI[2][4][4], accP[2][4][4];
    #pragma unroll
    for (int mt = 0; mt < 2; mt++)
        #pragma unroll
        for (int nt = 0; nt < 4; nt++)
            #pragma unroll
            for (int rr = 0; rr < 4; rr++) { accI[mt][nt][rr] = 0.f; accP[mt][nt][rr] = 0.f; }

    // ---- inner = Q @ K^T (K=64) ----
    #pragma unroll
    for (int kc = 0; kc < 64; kc += 8) {
        uint32_t A[2][4], B[4][2];
        #pragma unroll
        for (int mt = 0; mt < 2; mt++) {
            int base = arow + mt*16*68 + kc;
            A[mt][0] = __float_as_uint(bufQ[base]);
            A[mt][1] = __float_as_uint(bufQ[base + 8*68]);
            A[mt][2] = __float_as_uint(bufQ[base + 4]);
            A[mt][3] = __float_as_uint(bufQ[base + 8*68 + 4]);
        }
        #pragma unroll
        for (int nt = 0; nt < 4; nt++) {
            int base = brow + nt*8*68 + kc;
            B[nt][0] = __float_as_uint(bufK[base]);
            B[nt][1] = __float_as_uint(bufK[base + 4]);
        }
        #pragma unroll
        for (int mt = 0; mt < 2; mt++)
            #pragma unroll
            for (int nt = 0; nt < 4; nt++)
                mma16n8k8(accI[mt][nt], A[mt], B[nt]);
    }
    __syncthreads();

    // ---- dots_prime = Qp @ Kp^T (K=256, 4 chunks of 64) ----
    for (int c = 0; c < 4; c++) {
        for (int t2 = tid; t2 < 2048; t2 += 512) {
            int r = t2 >> 4, c4 = (t2 & 15) << 2;
            int qrow = bh*TT + qi[r], krow = bh*TT + ki[r];
            float4 a = *(const float4*)&g_qp[(size_t)qrow*MM + c*64 + c4];
            float4 b = *(const float4*)&g_kp[(size_t)krow*MM + c*64 + c4];
            a.x = f2tf32(a.x); a.y = f2tf32(a.y); a.z = f2tf32(a.z); a.w = f2tf32(a.w);
            b.x = f2tf32(b.x); b.y = f2tf32(b.y); b.z = f2tf32(b.z); b.w = f2tf32(b.w);
            *(float4*)&bufQ[r*68 + c4] = a;
            *(float4*)&bufK[r*68 + c4] = b;
        }
        __syncthreads();
        #pragma unroll
        for (int kc = 0; kc < 64; kc += 8) {
            uint32_t A[2][4], B[4][2];
            #pragma unroll
            for (int mt = 0; mt < 2; mt++) {
                int base = arow + mt*16*68 + kc;
                A[mt][0] = __float_as_uint(bufQ[base]);
                A[mt][1] = __float_as_uint(bufQ[base + 8*68]);
                A[mt][2] = __float_as_uint(bufQ[base + 4]);
                A[mt][3] = __float_as_uint(bufQ[base + 8*68 + 4]);
            }
            #pragma unroll
            for (int nt = 0; nt < 4; nt++) {
                int base = brow + nt*8*68 + kc;
                B[nt][0] = __float_as_uint(bufK[base]);
                B[nt][1] = __float_as_uint(bufK[base + 4]);
            }
            #pragma unroll
            for (int mt = 0; mt < 2; mt++)
                #pragma unroll
                for (int nt = 0; nt < 4; nt++)
                    mma16n8k8(accP[mt][nt], A[mt], B[nt]);
        }
        __syncthreads();
    }

    // ---- epilogue: dup correction + lse + dots (overlays bufQ/bufK) ----
    const float LOGT[5] = {0.f, 0.f, 0.69314718056f, 1.09861228867f, 1.38629436112f};
    const float RCPT[5] = {1.f, 1.f, 0.5f, 0.33333333333f, 0.25f};
    int rows[4]; unsigned qbr[4]; float plsr[4];
    #pragma unroll
    for (int mt = 0; mt < 2; mt++)
        #pragma unroll
        for (int hh = 0; hh < 2; hh++) {
            int ri = mt*2 + hh;
            rows[ri] = wr*32 + mt*16 + hh*8 + g;
            qbr[ri] = qb[rows[ri]];
            plsr[ri] = pls[rows[ri]];
        }
    int cols[8]; unsigned kbc[8];
    #pragma unroll
    for (int nt = 0; nt < 4; nt++)
        #pragma unroll
        for (int p = 0; p < 2; p++) {
            int ci = nt*2 + p;
            cols[ci] = wc*32 + nt*8 + 2*t + p;
            kbc[ci] = kb[cols[ci]];
        }

    float rowm[4] = {-3.402823466e38f, -3.402823466e38f, -3.402823466e38f, -3.402823466e38f};
    #pragma unroll
    for (int mt = 0; mt < 2; mt++)
        #pragma unroll
        for (int nt = 0; nt < 4; nt++)
            #pragma unroll
            for (int hh = 0; hh < 2; hh++)
                #pragma unroll
                for (int p = 0; p < 2; p++) {
                    int ri = mt*2 + hh, ci = nt*2 + p, rr = hh*2 + p;
                    int cnt = __popc(__vcmpeq4(qbr[ri], kbc[ci])) >> 3;
                    float x = accI[mt][nt][rr] * TEMP - LOGT[cnt];
                    accI[mt][nt][rr] = x;
                    accP[mt][nt][rr] *= RCPT[cnt];
                    rowm[ri] = fmaxf(rowm[ri], x);
                }
    #pragma unroll
    for (int ri = 0; ri < 4; ri++) {
        rowm[ri] = fmaxf(rowm[ri], __shfl_xor_sync(0xffffffffu, rowm[ri], 1));
        rowm[ri] = fmaxf(rowm[ri], __shfl_xor_sync(0xffffffffu, rowm[ri], 2));
    }
    if (t == 0) {
        #pragma unroll
        for (int ri = 0; ri < 4; ri++) pmax[wc*128 + rows[ri]] = rowm[ri];
    }
    __syncthreads();

    float l[4], e2[4], rsum[4] = {0.f, 0.f, 0.f, 0.f};
    #pragma unroll
    for (int ri = 0; ri < 4; ri++) {
        int r0 = rows[ri];
        float lv = fmaxf(fmaxf(pmax[r0], pmax[128+r0]), fmaxf(pmax[256+r0], pmax[384+r0]));
        lv = fmaxf(lv, plsr[ri]);
        l[ri] = lv;
        e2[ri] = expf(plsr[ri] - lv);
    }
    #pragma unroll
    for (int mt = 0; mt < 2; mt++)
        #pragma unroll
        for (int nt = 0; nt < 4; nt++)
            #pragma unroll
            for (int hh = 0; hh < 2; hh++)
                #pragma unroll
                for (int p = 0; p < 2; p++) {
                    int ri = mt*2 + hh, ci = nt*2 + p, rr = hh*2 + p;
                    float d = expf(accI[mt][nt][rr] - l[ri]) - accP[mt][nt][rr] * e2[ri];
                    rsum[ri] += d;
                    dots[rows[ri]*129 + cols[ci]] = d;
                }
    #pragma unroll
    for (int ri = 0; ri < 4; ri++) {
        rsum[ri] += __shfl_xor_sync(0xffffffffu, rsum[ri], 1);
        rsum[ri] += __shfl_xor_sync(0xffffffffu, rsum[ri], 2);
    }
    if (t == 0) {
        #pragma unroll
        for (int ri = 0; ri < 4; ri++) psum[wc*128 + rows[ri]] = rsum[ri];
    }
    __syncthreads();
    if (wc == 0 && t == 0) {
        #pragma unroll
        for (int ri = 0; ri < 4; ri++) {
            int r0 = rows[ri];
            float stot = psum[r0] + psum[128+r0] + psum[256+r0] + psum[384+r0];
            int q0 = qi[r0];
            g_logits[hb*TT + q0] = l[ri];
            g_dsum[hb*TT + q0]   = stot;
        }
    }

    // ---- so = dots @ s_v (SIMT) ----
    int cx = tid & 15, ry = tid >> 4;
    float acc2[4][4];
    #pragma unroll
    for (int i = 0; i < 4; i++)
        #pragma unroll
        for (int dd = 0; dd < 4; dd++) acc2[i][dd] = 0.f;
    #pragma unroll 4
    for (int j = 0; j < 128; j++) {
        float4 v4 = *(const float4*)&sv[j*68 + cx*4];
        #pragma unroll
        for (int i = 0; i < 4; i++) {
            float dij = dots[(ry*4+i)*129 + j];
            acc2[i][0] = fmaf(dij, v4.x, acc2[i][0]);
            acc2[i][1] = fmaf(dij, v4.y, acc2[i][1]);
            acc2[i][2] = fmaf(dij, v4.z, acc2[i][2]);
            acc2[i][3] = fmaf(dij, v4.w, acc2[i][3]);
        }
    }
    #pragma unroll
    for (int i = 0; i < 4; i++) {
        int q0 = qi[ry*4+i];
        *(float4*)&g_o[((size_t)(hb*TT + q0))*EE + cx*4] =
            make_float4(acc2[i][0], acc2[i][1], acc2[i][2], acc2[i][3]);
    }
}

// ---------------- K13: combine across hashes + global correction ----------------
__global__ void k_combine(float* __restrict__ out) {
    int tid = threadIdx.x;
    int row = blockIdx.x * 4 + (tid >> 6);
    int d = tid & 63;
    int bh = row >> 12, t = row & 4095;
    float l[NHSH];
    #pragma unroll
    for (int h = 0; h < NHSH; h++) l[h] = g_logits[(h*BHN+bh)*TT + t];
    float mx = fmaxf(fmaxf(l[0], l[1]), fmaxf(l[2], l[3]));
    float se = 0.f;
    #pragma unroll
    for (int h = 0; h < NHSH; h++) se += expf(l[h] - mx);
    float nls = mx + logf(se);
    float o = 0.f, nr = 0.f;
    #pragma unroll
    for (int h = 0; h < NHSH; h++) {
        float p = expf(l[h] - nls);
        o  = fmaf(g_o[((size_t)((h*BHN+bh)*TT + t))*EE + d], p, o);
        nr = fmaf(g_dsum[(h*BHN+bh)*TT + t], p, nr);
    }
    float ps = expf(g_qls[row] + g_kls[bh] - nls);
    o  = fmaf(g_qkv[row*EE+d], ps, o);
    nr = fmaf(g_qk1[row], ps, nr);
    o /= fmaxf(nr, 1e-6f);
    int b = bh >> 3, hh = bh & 7;
    out[((b*TT + t)*HH + hh)*EE + d] = o;
}

// ---------------- launch ----------------
extern "C" void kernel_launch(void* const* d_in, const int* in_sizes, int n_in,
                              void* d_out, int out_size) {
    const float* q     = (const float*)d_in[0];
    const float* k     = (const float*)d_in[1];
    const float* v     = (const float*)d_in[2];
    const float* proj  = (const float*)d_in[3];
    const float* alpha = (const float*)d_in[4];
    const float* beta  = (const float*)d_in[5];
    float* out = (float*)d_out;

    cudaFuncSetAttribute(k_feats_q, cudaFuncAttributeMaxDynamicSharedMemorySize, (64+9)*4);
    cudaFuncSetAttribute(k_feats_k, cudaFuncAttributeMaxDynamicSharedMemorySize, (64+9)*4);
    cudaFuncSetAttribute(k_qkvker,  cudaFuncAttributeMaxDynamicSharedMemorySize, 64*QKV_PITCH*4);
    cudaFuncSetAttribute(k_bucket,  cudaFuncAttributeMaxDynamicSharedMemorySize, BK_FLOATS*4);

    k_transpose<<<BHT/4, 256>>>(q, k, v);
    k_maxnorm<<<BHN, 256>>>();
    k_hash<<<BHT/8, 256>>>(alpha, beta);
    k_sort<<<2*NHSH*BHN, 512>>>();
    k_feats_q<<<BHT/16, 256, (64+9)*4>>>(proj);
    k_feats_k<<<BHT/16, 256, (64+9)*4>>>(proj);
    k_kls<<<BHN, 256>>>();
    k_kexp<<<(BHT*MM/4)/256, 256>>>();
    k_zero<<<(BHN*MM*EE + 255)/256, 256>>>();
    k_kvker<<<dim3(TT/128, BHN), 256>>>();
    k_qkvker<<<BHN*32, 256, 64*QKV_PITCH*4>>>();
    k_qk1ker<<<BHT/8, 256>>>();
    k_bucket<<<NHSH*BHN*NB, 512, BK_FLOATS*4>>>();
    k_combine<<<BHT/4, 256>>>(out);
}

// round 8
// speedup vs baseline: 1.1221x; 1.1221x over previous
#include <cuda_runtime.h>
#include <cuda_bf16.h>
#include <math.h>
#include <stdint.h>

// ---------------- problem constants ----------------
#define BB   2
#define TT   4096
#define HH   8
#define EE   64
#define MM   256
#define NHSH 4
#define BHN  16            // B*H
#define BHT  (BHN*TT)      // 65536
#define NB   32            // buckets per (hash, bh)
#define BS   128           // bucket size

#define TEMP   0.125f                 // 1/sqrt(64)
#define DN     0.3535533905932738f    // sqrt(TEMP)
#define RATIO  0.0625f                // 256^-0.5

// ---------------- scratch (device globals; no runtime alloc) ----------------
__device__ float g_q[BHT*EE];
__device__ float g_k[BHT*EE];
__device__ float g_v[BHT*EE];
__device__ float g_qn2[BHT], g_kn2[BHT];
__device__ float g_MQ2[BHN], g_MK2[BHN];
__device__ unsigned long long g_qkeys[NHSH*BHT];
__device__ unsigned long long g_kkeys[NHSH*BHT];
__device__ int g_qpos[NHSH*BHT], g_kpos[NHSH*BHT];
__device__ int g_qrev[NHSH*BHT], g_krev[NHSH*BHT];
__device__ float g_qp[BHT*MM];         // q_prime
__device__ float g_kp[BHT*MM];         // k logv then k_prime
__device__ float g_qls[BHT];           // per-row q stabilizer
__device__ float g_krowmax[BHT];
__device__ float g_kls[BHN];           // per-bh k stabilizer
__device__ float g_kv[BHN*MM*EE];
__device__ float g_ksum[BHN*MM];
__device__ float g_qkv[BHT*EE];
__device__ float g_qk1[BHT];
__device__ float g_o[NHSH*BHT*EE];     // per-hash bucket outputs (scattered)
__device__ float g_logits[NHSH*BHT];
__device__ float g_dsum[NHSH*BHT];

// ---------------- helpers ----------------
__device__ __forceinline__ unsigned f2sortable(float f) {
    unsigned u = __float_as_uint(f);
    return (u & 0x80000000u) ? ~u : (u | 0x80000000u);
}

// 16B-group XOR swizzle: tile is [64 e][128 r] floats; r4 = r>>2 in 0..31
__device__ __forceinline__ int swz(int e, int r4) { return ((r4 ^ (e & 31)) << 2); }

// packed f32x2 FMA (Blackwell FFMA2 pipe)
__device__ __forceinline__ unsigned long long pk2(float lo, float hi) {
    unsigned long long r;
    asm("mov.b64 %0, {%1, %2};" : "=l"(r) : "f"(lo), "f"(hi));
    return r;
}
__device__ __forceinline__ void unpk2(unsigned long long v, float& lo, float& hi) {
    asm("mov.b64 {%0, %1}, %2;" : "=f"(lo), "=f"(hi) : "l"(v));
}
__device__ __forceinline__ void fma2(unsigned long long& d, unsigned long long a,
                                     unsigned long long b) {
    asm("fma.rn.f32x2 %0, %1, %2, %0;" : "+l"(d) : "l"(a), "l"(b));
}

// ---------------- K0: transpose (B,T,H,E)->(bh,T,E) + row norms ----------------
__global__ void k_transpose(const float* __restrict__ q, const float* __restrict__ k,
                            const float* __restrict__ v) {
    __shared__ float sred[8][2];
    int tid = threadIdx.x;
    int g = tid >> 6;          // 0..3 rows per block
    int e = tid & 63;
    int row = blockIdx.x * 4 + g;
    int bh = row >> 12;
    int t  = row & 4095;
    int b = bh >> 3, h = bh & 7;
    int src = ((b * TT + t) * HH + h) * EE + e;
    float qv = q[src], kv2 = k[src], vv = v[src];
    g_q[row*EE+e] = qv; g_k[row*EE+e] = kv2; g_v[row*EE+e] = vv;
    float sq = qv*qv, sk = kv2*kv2;
    #pragma unroll
    for (int m = 16; m > 0; m >>= 1) {
        sq += __shfl_xor_sync(0xffffffffu, sq, m);
        sk += __shfl_xor_sync(0xffffffffu, sk, m);
    }
    int w = tid >> 5;
    if ((tid & 31) == 0) { sred[w][0] = sq; sred[w][1] = sk; }
    __syncthreads();
    if (e == 0) {
        g_qn2[row] = sred[2*g][0] + sred[2*g+1][0];
        g_kn2[row] = sred[2*g][1] + sred[2*g+1][1];
    }
}

// ---------------- K1: per-bh max of squared norms ----------------
__global__ void k_maxnorm() {
    __shared__ float s[8][2];
    int bh = blockIdx.x, tid = threadIdx.x;
    float mq = 0.f, mk = 0.f;
    for (int t = tid; t < TT; t += 256) {
        mq = fmaxf(mq, g_qn2[bh*TT+t]);
        mk = fmaxf(mk, g_kn2[bh*TT+t]);
    }
    #pragma unroll
    for (int m = 16; m > 0; m >>= 1) {
        mq = fmaxf(mq, __shfl_xor_sync(0xffffffffu, mq, m));
        mk = fmaxf(mk, __shfl_xor_sync(0xffffffffu, mk, m));
    }
    if ((tid & 31) == 0) { s[tid>>5][0] = mq; s[tid>>5][1] = mk; }
    __syncthreads();
    if (tid == 0) {
        float a = s[0][0], b2 = s[0][1];
        for (int i = 1; i < 8; i++) { a = fmaxf(a, s[i][0]); b2 = fmaxf(b2, s[i][1]); }
        g_MQ2[bh] = a; g_MK2[bh] = b2;
    }
}

// ---------------- K2: LSH hash keys (packed sortable key | index) ----------------
__global__ void k_hash(const float* __restrict__ alpha, const float* __restrict__ beta) {
    int w = threadIdx.x >> 5, lane = threadIdx.x & 31;
    int row = blockIdx.x * 8 + w;
    int bh = row >> 12, t = row & 4095;
    float aq[NHSH] = {0,0,0,0}, ak[NHSH] = {0,0,0,0};
    for (int e = lane; e < EE; e += 32) {
        float xq = g_q[row*EE+e], xk = g_k[row*EE+e];
        #pragma unroll
        for (int h = 0; h < NHSH; h++) {
            float al = alpha[e*NHSH+h];
            aq[h] = fmaf(xq, al, aq[h]);
            ak[h] = fmaf(xk, al, ak[h]);
        }
    }
    #pragma unroll
    for (int m = 16; m > 0; m >>= 1) {
        #pragma unroll
        for (int h = 0; h < NHSH; h++) {
            aq[h] += __shfl_xor_sync(0xffffffffu, aq[h], m);
            ak[h] += __shfl_xor_sync(0xffffffffu, ak[h], m);
        }
    }
    if (lane == 0) {
        float s2 = g_MQ2[bh] + g_MK2[bh];
        float extq = sqrtf(fmaxf(s2 - g_qn2[row], 0.f));
        float extk = sqrtf(fmaxf(s2 - g_kn2[row], 0.f));
        #pragma unroll
        for (int h = 0; h < NHSH; h++) {
            float hq = aq[h] + extq * alpha[64*NHSH+h] + beta[h];
            float hk = ak[h] + extk * alpha[65*NHSH+h] + beta[h];
            g_qkeys[(h*BHN+bh)*TT + t] = (((unsigned long long)f2sortable(hq)) << 32) | (unsigned)t;
            g_kkeys[(h*BHN+bh)*TT + t] = (((unsigned long long)f2sortable(hk)) << 32) | (unsigned)t;
        }
    }
}

// ---------------- K3: bitonic argsort (stable via packed index) ----------------
__global__ void k_sort() {
    __shared__ unsigned long long s[TT];
    int which = blockIdx.x >> 6;                 // 0 = q, 1 = k
    int hb = blockIdx.x & 63;
    const unsigned long long* src = which ? g_kkeys : g_qkeys;
    int* pos = which ? g_kpos : g_qpos;
    int* rev = which ? g_krev : g_qrev;
    int base = hb * TT;
    for (int i = threadIdx.x; i < TT; i += 512) s[i] = src[base+i];
    for (int k2 = 2; k2 <= TT; k2 <<= 1) {
        for (int j = k2 >> 1; j > 0; j >>= 1) {
            __syncthreads();
            for (int i = threadIdx.x; i < TT; i += 512) {
                int ixj = i ^ j;
                if (ixj > i) {
                    unsigned long long a = s[i], b = s[ixj];
                    bool asc = ((i & k2) == 0);
                    if ((a > b) == asc) { s[i] = b; s[ixj] = a; }
                }
            }
        }
    }
    __syncthreads();
    for (int i = threadIdx.x; i < TT; i += 512) {
        int orig = (int)(s[i] & 0xffffffffu);
        pos[base+i] = orig;
        rev[base+orig] = i;
    }
}

// ---------------- K4: q Performer features (per-row stabilizer) ----------------
__global__ void k_feats_q(const float* __restrict__ proj) {
    extern __shared__ float sm[];
    float* qrow = sm;       // 64
    float* red  = sm + 64;  // 9
    int tid = threadIdx.x;
    float pcol[EE];
    const float4* p4 = (const float4*)(proj + tid*EE);
    #pragma unroll
    for (int i = 0; i < 16; i++) {
        float4 w = p4[i];
        pcol[4*i] = w.x; pcol[4*i+1] = w.y; pcol[4*i+2] = w.z; pcol[4*i+3] = w.w;
    }
    int row0 = blockIdx.x * 16;
    for (int r = 0; r < 16; r++) {
        int row = row0 + r;
        if (tid < 64) qrow[tid] = g_q[row*EE+tid];
        __syncthreads();
        float dot = 0.f;
        #pragma unroll
        for (int e = 0; e < EE; e++) dot = fmaf(qrow[e], pcol[e], dot);
        float logv = DN * dot - 0.0625f * g_qn2[row];   // 0.5*dn^2 = 0.0625
        float mx = logv;
        #pragma unroll
        for (int m = 16; m > 0; m >>= 1) mx = fmaxf(mx, __shfl_xor_sync(0xffffffffu, mx, m));
        if ((tid & 31) == 0) red[tid>>5] = mx;
        __syncthreads();
        if (tid == 0) {
            float a = red[0];
            for (int i = 1; i < 8; i++) a = fmaxf(a, red[i]);
            red[8] = a;
        }
        __syncthreads();
        float stab = red[8];
        g_qp[row*MM+tid] = __expf(logv - stab) * RATIO;
        if (tid == 0) g_qls[row] = stab;
        __syncthreads();
    }
}

// ---------------- K5: k features pass1 (logv + row max) ----------------
__global__ void k_feats_k(const float* __restrict__ proj) {
    extern __shared__ float sm[];
    float* krow = sm;
    float* red  = sm + 64;
    int tid = threadIdx.x;
    float pcol[EE];
    const float4* p4 = (const float4*)(proj + tid*EE);
    #pragma unroll
    for (int i = 0; i < 16; i++) {
        float4 w = p4[i];
        pcol[4*i] = w.x; pcol[4*i+1] = w.y; pcol[4*i+2] = w.z; pcol[4*i+3] = w.w;
    }
    int row0 = blockIdx.x * 16;
    for (int r = 0; r < 16; r++) {
        int row = row0 + r;
        if (tid < 64) krow[tid] = g_k[row*EE+tid];
        __syncthreads();
        float dot = 0.f;
        #pragma unroll
        for (int e = 0; e < EE; e++) dot = fmaf(krow[e], pcol[e], dot);
        float logv = DN * dot - 0.0625f * g_kn2[row];
        float mx = logv;
        #pragma unroll
        for (int m = 16; m > 0; m >>= 1) mx = fmaxf(mx, __shfl_xor_sync(0xffffffffu, mx, m));
        if ((tid & 31) == 0) red[tid>>5] = mx;
        __syncthreads();
        if (tid == 0) {
            float a = red[0];
            for (int i = 1; i < 8; i++) a = fmaxf(a, red[i]);
            red[8] = a;
        }
        __syncthreads();
        g_kp[row*MM+tid] = logv;
        if (tid == 0) g_krowmax[row] = red[8];
        __syncthreads();
    }
}

// ---------------- K6: per-bh k stabilizer ----------------
__global__ void k_kls() {
    __shared__ float s[8];
    int bh = blockIdx.x, tid = threadIdx.x;
    float m = -3.402823466e38f;
    for (int t = tid; t < TT; t += 256) m = fmaxf(m, g_krowmax[bh*TT+t]);
    #pragma unroll
    for (int mm = 16; mm > 0; mm >>= 1) m = fmaxf(m, __shfl_xor_sync(0xffffffffu, m, mm));
    if ((tid & 31) == 0) s[tid>>5] = m;
    __syncthreads();
    if (tid == 0) {
        float a = s[0];
        for (int i = 1; i < 8; i++) a = fmaxf(a, s[i]);
        g_kls[bh] = a;
    }
}

// ---------------- K7: k_prime = exp(logv - kls)*ratio ----------------
__global__ void k_kexp() {
    int idx4 = blockIdx.x * 256 + threadIdx.x;      // float4 index
    int bh = idx4 >> 18;                            // (4096*256)/4 = 2^18 per bh
    float kls = g_kls[bh];
    float4* p = (float4*)g_kp;
    float4 x = p[idx4];
    x.x = __expf(x.x - kls) * RATIO;
    x.y = __expf(x.y - kls) * RATIO;
    x.z = __expf(x.z - kls) * RATIO;
    x.w = __expf(x.w - kls) * RATIO;
    p[idx4] = x;
}

// ---------------- K8: zero kv/ksum ----------------
__global__ void k_zero() {
    int i = blockIdx.x * 256 + threadIdx.x;
    if (i < BHN*MM*EE) g_kv[i] = 0.f;
    if (i < BHN*MM) g_ksum[i] = 0.f;
}

// ---------------- K9: kv = k_prime^T @ v, ksum = sum_s k_prime ----------------
__global__ void k_kvker() {
    __shared__ float vs[128*EE];
    int bh = blockIdx.y, sc = blockIdx.x, tid = threadIdx.x;
    int s0 = sc * 128;
    for (int i = tid; i < 128*EE; i += 256) vs[i] = g_v[(bh*TT+s0)*EE + i];
    __syncthreads();
    float acc[EE];
    #pragma unroll
    for (int d = 0; d < EE; d++) acc[d] = 0.f;
    float asum = 0.f;
    int m = tid;
    const float* kp = g_kp + ((size_t)(bh*TT+s0))*MM + m;
    for (int s = 0; s < 128; s++) {
        float kpv = kp[(size_t)s*MM];
        asum += kpv;
        #pragma unroll
        for (int d = 0; d < EE; d++) acc[d] = fmaf(kpv, vs[s*EE+d], acc[d]);
    }
    float* kvp = g_kv + (bh*MM+m)*EE;
    #pragma unroll
    for (int d = 0; d < EE; d++) atomicAdd(kvp + d, acc[d]);
    atomicAdd(g_ksum + bh*MM+m, asum);
}

// ---------------- K10: qkv = q_prime @ kv (kv transposed in smem, f32x2) ----------------
#define QKV_PITCH 260
__global__ void __launch_bounds__(256) k_qkvker() {
    extern __shared__ float kvT[];   // 64 * 260 floats
    int tid = threadIdx.x;
    int bh = blockIdx.x >> 5;        // 32 blocks per bh
    int t0 = (blockIdx.x & 31) * 128;
    for (int idx = tid; idx < MM*16; idx += 256) {
        int m = idx >> 4, d4 = idx & 15;
        float4 w = *(const float4*)&g_kv[(bh*MM+m)*EE + d4*4];
        kvT[(d4*4+0)*QKV_PITCH+m] = w.x;
        kvT[(d4*4+1)*QKV_PITCH+m] = w.y;
        kvT[(d4*4+2)*QKV_PITCH+m] = w.z;
        kvT[(d4*4+3)*QKV_PITCH+m] = w.w;
    }
    __syncthreads();
    int dl = tid & 63, rg = tid >> 6;
    for (int s = 0; s < 8; s++) {
        unsigned long long acc2[4];
        #pragma unroll
        for (int r = 0; r < 4; r++) acc2[r] = 0ull;
        int rowb = bh*TT + t0 + s*16;
        #pragma unroll 4
        for (int m4 = 0; m4 < 64; m4++) {
            float4 kv4 = *(const float4*)&kvT[dl*QKV_PITCH + m4*4];
            unsigned long long kp0 = pk2(kv4.x, kv4.y);
            unsigned long long kp1 = pk2(kv4.z, kv4.w);
            #pragma unroll
            for (int r = 0; r < 4; r++) {
                float4 q4 = *(const float4*)&g_qp[(size_t)(rowb + rg + r*4)*MM + m4*4];
                fma2(acc2[r], pk2(q4.x, q4.y), kp0);
                fma2(acc2[r], pk2(q4.z, q4.w), kp1);
            }
        }
        #pragma unroll
        for (int r = 0; r < 4; r++) {
            float lo, hi; unpk2(acc2[r], lo, hi);
            g_qkv[(size_t)(rowb + rg + r*4)*EE + dl] = lo + hi;
        }
    }
}

// ---------------- K11: qk1 = q_prime . ksum ----------------
__global__ void k_qk1ker() {
    int w = threadIdx.x >> 5, lane = threadIdx.x & 31;
    int row = blockIdx.x * 8 + w;
    int bh = row >> 12;
    const float* qp = g_qp + (size_t)row*MM;
    const float* ks = g_ksum + bh*MM;
    float a = 0.f;
    for (int m = lane; m < MM; m += 32) a = fmaf(qp[m], ks[m], a);
    #pragma unroll
    for (int m = 16; m > 0; m >>= 1) a += __shfl_xor_sync(0xffffffffu, a, m);
    if (lane == 0) g_qk1[row] = a;
}

// ---------------- K12: per-bucket attention, f32x2 SIMT ----------------
// smem float layout (25728 floats = 102912 B):
//  bufA [0, 8192)     : e-major swizzled q tile / qp chunks  [64 e][128 r]
//  bufB [8192, 16384) : e-major swizzled k tile / kp chunks
//  dots overlays [0, 16384): 128 rows x 128, pitch 128
//  sv   [16384, 25088): row-major 128 x pitch 68
//  qi 25088, ki 25216, qb 25344, kb 25472, pls 25600
__global__ void __launch_bounds__(512, 1) k_bucket() {
    extern __shared__ float sm[];
    float* bufA = sm;
    float* bufB = sm + 8192;
    float* dots = sm;                       // pitch 128, overlays bufA+bufB
    float* sv   = sm + 16384;               // pitch 68
    int*      qi = (int*)(sm + 25088);
    int*      ki = (int*)(sm + 25216);
    unsigned* qb = (unsigned*)(sm + 25344);
    unsigned* kb = (unsigned*)(sm + 25472);
    float*   pls = sm + 25600;

    int tid = threadIdx.x;
    int n  = blockIdx.x & 31;
    int bh = (blockIdx.x >> 5) & 15;
    int h  = blockIdx.x >> 9;
    int hb = h * BHN + bh;

    if (tid < 128) qi[tid] = g_qpos[hb*TT + n*128 + tid];
    else if (tid < 256) ki[tid-128] = g_kpos[hb*TT + n*128 + (tid-128)];
    __syncthreads();

    // load q,k (swizzled transposed) and v (row-major), plus bucket ids
    for (int idx = tid; idx < 128*16; idx += 512) {
        int r = idx >> 4, e4 = idx & 15;
        int qrow = bh*TT + qi[r], krow = bh*TT + ki[r];
        float4 a = *(const float4*)&g_q[qrow*EE + e4*4];
        float4 b = *(const float4*)&g_k[krow*EE + e4*4];
        float4 c = *(const float4*)&g_v[krow*EE + e4*4];
        int r4 = r >> 2, rl = r & 3;
        #pragma unroll
        for (int u = 0; u < 4; u++) {
            int e = e4*4 + u;
            bufA[e*128 + swz(e, r4) + rl] = ((const float*)&a)[u];
            bufB[e*128 + swz(e, r4) + rl] = ((const float*)&b)[u];
        }
        *(float4*)&sv[r*68 + e4*4] = c;
    }
    if (tid < 128) {
        int q0 = qi[tid];
        unsigned pb = 0;
        #pragma unroll
        for (int hh = 0; hh < NHSH; hh++)
            pb |= ((unsigned)(g_qrev[(hh*BHN+bh)*TT + q0] >> 7)) << (8*hh);
        qb[tid] = pb;
        pls[tid] = g_qls[bh*TT + q0] + g_kls[bh];
    } else if (tid < 256) {
        int j = tid - 128;
        int k0 = ki[j];
        unsigned pb = 0;
        #pragma unroll
        for (int hh = 0; hh < NHSH; hh++)
            pb |= ((unsigned)(g_krev[(hh*BHN+bh)*TT + k0] >> 7)) << (8*hh);
        kb[j] = pb;
    }
    __syncthreads();

    int tx = tid & 15, ty = tid >> 4;   // rows ty*4+i, cols tx*8+j
    unsigned long long accI2[4][4], accP2[4][4];
    #pragma unroll
    for (int i = 0; i < 4; i++)
        #pragma unroll
        for (int jp = 0; jp < 4; jp++) { accI2[i][jp] = 0ull; accP2[i][jp] = 0ull; }

    // inner = s_q @ s_k^T (K=64), f32x2 packed along j
    #pragma unroll 2
    for (int e = 0; e < 64; e++) {
        float4 a4  = *(const float4*)&bufA[e*128 + swz(e, ty)];
        float4 b4a = *(const float4*)&bufB[e*128 + swz(e, 2*tx)];
        float4 b4b = *(const float4*)&bufB[e*128 + swz(e, 2*tx+1)];
        unsigned long long bp[4] = { pk2(b4a.x, b4a.y), pk2(b4a.z, b4a.w),
                                     pk2(b4b.x, b4b.y), pk2(b4b.z, b4b.w) };
        const float* av = (const float*)&a4;
        #pragma unroll
        for (int i = 0; i < 4; i++) {
            unsigned long long ad = pk2(av[i], av[i]);
            #pragma unroll
            for (int jp = 0; jp < 4; jp++) fma2(accI2[i][jp], ad, bp[jp]);
        }
    }
    __syncthreads();

    // dots_prime = sq_p @ sk_p^T (K=256, 4 chunks of 64 reusing bufA/bufB)
    for (int c = 0; c < 4; c++) {
        for (int idx = tid; idx < 128*16; idx += 512) {
            int r = idx >> 4, e4 = idx & 15;
            float4 a = *(const float4*)&g_qp[((size_t)(bh*TT+qi[r]))*MM + c*64 + e4*4];
            float4 b = *(const float4*)&g_kp[((size_t)(bh*TT+ki[r]))*MM + c*64 + e4*4];
            int r4 = r >> 2, rl = r & 3;
            #pragma unroll
            for (int u = 0; u < 4; u++) {
                int e = e4*4 + u;
                bufA[e*128 + swz(e, r4) + rl] = ((const float*)&a)[u];
                bufB[e*128 + swz(e, r4) + rl] = ((const float*)&b)[u];
            }
        }
        __syncthreads();
        #pragma unroll 2
        for (int e = 0; e < 64; e++) {
            float4 a4  = *(const float4*)&bufA[e*128 + swz(e, ty)];
            float4 b4a = *(const float4*)&bufB[e*128 + swz(e, 2*tx)];
            float4 b4b = *(const float4*)&bufB[e*128 + swz(e, 2*tx+1)];
            unsigned long long bp[4] = { pk2(b4a.x, b4a.y), pk2(b4a.z, b4a.w),
                                         pk2(b4b.x, b4b.y), pk2(b4b.z, b4b.w) };
            const float* av = (const float*)&a4;
            #pragma unroll
            for (int i = 0; i < 4; i++) {
                unsigned long long ad = pk2(av[i], av[i]);
                #pragma unroll
                for (int jp = 0; jp < 4; jp++) fma2(accP2[i][jp], ad, bp[jp]);
            }
        }
        __syncthreads();
    }

    // unpack accumulators
    float accI[4][8], accP[4][8];
    #pragma unroll
    for (int i = 0; i < 4; i++)
        #pragma unroll
        for (int jp = 0; jp < 4; jp++) {
            unpk2(accI2[i][jp], accI[i][2*jp], accI[i][2*jp+1]);
            unpk2(accP2[i][jp], accP[i][2*jp], accP[i][2*jp+1]);
        }

    // duplicate-count correction + per-row lse + dots (overlays bufA/bufB)
    const float LOGT[5] = {0.f, 0.f, 0.69314718056f, 1.09861228867f, 1.38629436112f};
    const float RCPT[5] = {1.f, 1.f, 0.5f, 0.33333333333f, 0.25f};
    unsigned qb_r[4], kb_c[8];
    float plsr[4], rowm[4];
    #pragma unroll
    for (int i = 0; i < 4; i++) {
        qb_r[i] = qb[ty*4+i]; plsr[i] = pls[ty*4+i]; rowm[i] = -3.402823466e38f;
    }
    #pragma unroll
    for (int j = 0; j < 8; j++) kb_c[j] = kb[tx*8+j];

    #pragma unroll
    for (int i = 0; i < 4; i++)
        #pragma unroll
        for (int j = 0; j < 8; j++) {
            int cnt = __popc(__vcmpeq4(qb_r[i], kb_c[j])) >> 3;
            float inner = accI[i][j] * TEMP - LOGT[cnt];
            accI[i][j] = inner;
            accP[i][j] *= RCPT[cnt];
            rowm[i] = fmaxf(rowm[i], inner);
        }
    #pragma unroll
    for (int i = 0; i < 4; i++)
        #pragma unroll
        for (int m = 8; m >= 1; m >>= 1)
            rowm[i] = fmaxf(rowm[i], __shfl_xor_sync(0xffffffffu, rowm[i], m));

    #pragma unroll
    for (int i = 0; i < 4; i++) {
        float l = fmaxf(rowm[i], plsr[i]);
        float e2 = __expf(plsr[i] - l);
        float s = 0.f;
        float dv[8];
        #pragma unroll
        for (int j = 0; j < 8; j++) {
            float d = __expf(accI[i][j] - l) - accP[i][j] * e2;
            s += d;
            dv[j] = d;
        }
        *(float4*)&dots[(ty*4+i)*128 + tx*8]     = make_float4(dv[0], dv[1], dv[2], dv[3]);
        *(float4*)&dots[(ty*4+i)*128 + tx*8 + 4] = make_float4(dv[4], dv[5], dv[6], dv[7]);
        #pragma unroll
        for (int m = 8; m >= 1; m >>= 1) s += __shfl_xor_sync(0xffffffffu, s, m);
        if (tx == 0) {
            int q0 = qi[ty*4+i];
            g_logits[hb*TT + q0] = l;
            g_dsum[hb*TT + q0]   = s;
        }
    }
    __syncthreads();

    // epilogue: so = dots @ s_v ; f32x2 along d
    int cx = tid & 15, ry = tid >> 4;
    unsigned long long acc2p[4][2];
    #pragma unroll
    for (int i = 0; i < 4; i++) { acc2p[i][0] = 0ull; acc2p[i][1] = 0ull; }
    #pragma unroll 4
    for (int j = 0; j < 128; j++) {
        float4 v4 = *(const float4*)&sv[j*68 + cx*4];
        unsigned long long vp0 = pk2(v4.x, v4.y);
        unsigned long long vp1 = pk2(v4.z, v4.w);
        #pragma unroll
        for (int i = 0; i < 4; i++) {
            float dij = dots[(ry*4+i)*128 + j];
            unsigned long long dd2 = pk2(dij, dij);
            fma2(acc2p[i][0], dd2, vp0);
            fma2(acc2p[i][1], dd2, vp1);
        }
    }
    #pragma unroll
    for (int i = 0; i < 4; i++) {
        int q0 = qi[ry*4+i];
        float o0, o1, o2, o3;
        unpk2(acc2p[i][0], o0, o1);
        unpk2(acc2p[i][1], o2, o3);
        *(float4*)&g_o[((size_t)(hb*TT + q0))*EE + cx*4] = make_float4(o0, o1, o2, o3);
    }
}

// ---------------- K13: combine across hashes + global correction ----------------
__global__ void k_combine(float* __restrict__ out) {
    int tid = threadIdx.x;
    int row = blockIdx.x * 4 + (tid >> 6);
    int d = tid & 63;
    int bh = row >> 12, t = row & 4095;
    float l[NHSH];
    #pragma unroll
    for (int h = 0; h < NHSH; h++) l[h] = g_logits[(h*BHN+bh)*TT + t];
    float mx = fmaxf(fmaxf(l[0], l[1]), fmaxf(l[2], l[3]));
    float se = 0.f;
    #pragma unroll
    for (int h = 0; h < NHSH; h++) se += __expf(l[h] - mx);
    float nls = mx + __logf(se);
    float o = 0.f, nr = 0.f;
    #pragma unroll
    for (int h = 0; h < NHSH; h++) {
        float p = __expf(l[h] - nls);
        o  = fmaf(g_o[((size_t)((h*BHN+bh)*TT + t))*EE + d], p, o);
        nr = fmaf(g_dsum[(h*BHN+bh)*TT + t], p, nr);
    }
    float ps = __expf(g_qls[row] + g_kls[bh] - nls);
    o  = fmaf(g_qkv[row*EE+d], ps, o);
    nr = fmaf(g_qk1[row], ps, nr);
    o /= fmaxf(nr, 1e-6f);
    int b = bh >> 3, hh = bh & 7;
    out[((b*TT + t)*HH + hh)*EE + d] = o;
}

// ---------------- launch ----------------
extern "C" void kernel_launch(void* const* d_in, const int* in_sizes, int n_in,
                              void* d_out, int out_size) {
    const float* q     = (const float*)d_in[0];
    const float* k     = (const float*)d_in[1];
    const float* v     = (const float*)d_in[2];
    const float* proj  = (const float*)d_in[3];
    const float* alpha = (const float*)d_in[4];
    const float* beta  = (const float*)d_in[5];
    float* out = (float*)d_out;

    cudaFuncSetAttribute(k_feats_q, cudaFuncAttributeMaxDynamicSharedMemorySize, (64+9)*4);
    cudaFuncSetAttribute(k_feats_k, cudaFuncAttributeMaxDynamicSharedMemorySize, (64+9)*4);
    cudaFuncSetAttribute(k_qkvker,  cudaFuncAttributeMaxDynamicSharedMemorySize, 64*QKV_PITCH*4);
    cudaFuncSetAttribute(k_bucket,  cudaFuncAttributeMaxDynamicSharedMemorySize, 25728*4);

    k_transpose<<<BHT/4, 256>>>(q, k, v);
    k_maxnorm<<<BHN, 256>>>();
    k_hash<<<BHT/8, 256>>>(alpha, beta);
    k_sort<<<2*NHSH*BHN, 512>>>();
    k_feats_q<<<BHT/16, 256, (64+9)*4>>>(proj);
    k_feats_k<<<BHT/16, 256, (64+9)*4>>>(proj);
    k_kls<<<BHN, 256>>>();
    k_kexp<<<(BHT*MM/4)/256, 256>>>();
    k_zero<<<(BHN*MM*EE + 255)/256, 256>>>();
    k_kvker<<<dim3(TT/128, BHN), 256>>>();
    k_qkvker<<<BHN*32, 256, 64*QKV_PITCH*4>>>();
    k_qk1ker<<<BHT/8, 256>>>();
    k_bucket<<<NHSH*BHN*NB, 512, 25728*4>>>();
    k_combine<<<BHT/4, 256>>>(out);
}